// round 14
// baseline (speedup 1.0000x reference)
#include <cuda_runtime.h>
#include <cuda_bf16.h>
#include <cstdint>

#define NMAX 50000
#define EPS  1e-5f
#define PPB  32          // points per block (4 sub-batches of 8)
#define RSTB 144         // bf16 tile row stride in BYTES (64 bf16 data + pad)
#define LCHB 2304        // per-warp logits chunk bytes (== 16 A rows)
#define LRST 272         // logits row stride bytes (68 floats)

// ---------------- scratch (static device arrays: allocation-free) ----------
__device__ float g_q[NMAX * 64];
__device__ float g_k[NMAX * 64];
__device__ float g_v[NMAX * 64];

// ---------------- mma / ldmatrix helpers ------------------------------------
__device__ __forceinline__ uint32_t smem_u32(const void* p) {
    uint32_t a;
    asm("{ .reg .u64 t; cvta.to.shared.u64 t, %1; cvt.u32.u64 %0, t; }" : "=r"(a) : "l"(p));
    return a;
}
__device__ __forceinline__ void ldsm4(uint32_t* r, uint32_t addr) {
    asm volatile("ldmatrix.sync.aligned.m8n8.x4.shared.b16 {%0,%1,%2,%3},[%4];"
        : "=r"(r[0]), "=r"(r[1]), "=r"(r[2]), "=r"(r[3]) : "r"(addr));
}
__device__ __forceinline__ void ldsm4t(uint32_t* r, uint32_t addr) {
    asm volatile("ldmatrix.sync.aligned.m8n8.x4.trans.shared.b16 {%0,%1,%2,%3},[%4];"
        : "=r"(r[0]), "=r"(r[1]), "=r"(r[2]), "=r"(r[3]) : "r"(addr));
}
__device__ __forceinline__ void mma_bf16(float* c, const uint32_t* a, const uint32_t* b) {
    asm volatile("mma.sync.aligned.m16n8k16.row.col.f32.bf16.bf16.f32 "
        "{%0,%1,%2,%3},{%4,%5,%6,%7},{%8,%9},{%0,%1,%2,%3};"
        : "+f"(c[0]), "+f"(c[1]), "+f"(c[2]), "+f"(c[3])
        : "r"(a[0]), "r"(a[1]), "r"(a[2]), "r"(a[3]), "r"(b[0]), "r"(b[1]));
}
__device__ __forceinline__ void split2(float x0, float x1, uint32_t& hi, uint32_t& lo) {
    __nv_bfloat162 h = __floats2bfloat162_rn(x0, x1);
    hi = *(uint32_t*)&h;
    __nv_bfloat162 l = __floats2bfloat162_rn(x0 - __bfloat162float(h.x),
                                             x1 - __bfloat162float(h.y));
    lo = *(uint32_t*)&l;
}
__device__ __forceinline__ void split8(const float* o, uint4& h4, uint4& l4) {
    split2(o[0], o[1], h4.x, l4.x);
    split2(o[2], o[3], h4.y, l4.y);
    split2(o[4], o[5], h4.z, l4.z);
    split2(o[6], o[7], h4.w, l4.w);
}

// GEMM core: acc(16x64 per warp) = Ahi*Bhi + Alo*Bhi + Ahi*Blo
__device__ __forceinline__ void gemm_frags(
    float acc[8][4], const uint32_t Ah[4][4], const uint32_t Al[4][4],
    uint32_t wbaseH, uint32_t wbaseL, int lid)
{
    #pragma unroll
    for (int nt = 0; nt < 8; nt++)
        #pragma unroll
        for (int i = 0; i < 4; i++) acc[nt][i] = 0.f;
    const uint32_t colb = (uint32_t)(lid & 15) * RSTB + (uint32_t)(lid >> 4) * 16;
    #pragma unroll
    for (int p = 0; p < 4; p++) {
        const uint32_t cofs = colb + (uint32_t)(p * 32);
        uint32_t bh[4][4], bl[4][4];
        #pragma unroll
        for (int k = 0; k < 4; k++) ldsm4t(bh[k], wbaseH + (uint32_t)(k * 16) * RSTB + cofs);
        #pragma unroll
        for (int k = 0; k < 4; k++) { mma_bf16(acc[2*p], Ah[k], &bh[k][0]); mma_bf16(acc[2*p+1], Ah[k], &bh[k][2]); }
        #pragma unroll
        for (int k = 0; k < 4; k++) ldsm4t(bl[k], wbaseL + (uint32_t)(k * 16) * RSTB + cofs);
        #pragma unroll
        for (int k = 0; k < 4; k++) { mma_bf16(acc[2*p], Al[k], &bh[k][0]); mma_bf16(acc[2*p+1], Al[k], &bh[k][2]); }
        #pragma unroll
        for (int k = 0; k < 4; k++) { mma_bf16(acc[2*p], Ah[k], &bl[k][0]); mma_bf16(acc[2*p+1], Ah[k], &bl[k][2]); }
    }
}

// ======================= kernel 1: q/k/v projections (HMMA) =================
#define QOFF_W    0              // 3 x (hi 9216 + lo 9216) = 55296
#define QOFF_AH   55296
#define QOFF_AL   73728
#define QOFF_BIAS 92160          // 192 floats
#define QSMEM_BYTES 92928

__global__ __launch_bounds__(256, 2) void qkv_kernel(
    const float* __restrict__ feat,
    const float* __restrict__ wq, const float* __restrict__ bq,
    const float* __restrict__ wk, const float* __restrict__ bk,
    const float* __restrict__ wv, const float* __restrict__ bv,
    int n)
{
    extern __shared__ char qsm[];
    float* qbias = (float*)(qsm + QOFF_BIAS);
    const int t   = threadIdx.x;
    const int wid = t >> 5;
    const int lid = t & 31;
    const int row0 = blockIdx.x * 128;
    const uint32_t sbase = smem_u32(qsm);

    const float* Wm[3] = { wq, wk, wv };
    const float* Bm[3] = { bq, bk, bv };

    for (int idx = t; idx < 384; idx += 256) {
        const int m  = idx / 128;
        const int rw = (idx & 127) >> 1;
        const int hf = (idx & 1) * 32;
        const float* w = Wm[m];
        char* dH = qsm + QOFF_W + m * 18432 + rw * RSTB;
        char* dL = dH + 9216;
        #pragma unroll
        for (int c8 = 0; c8 < 32; c8 += 8) {
            int c = hf + c8;
            float o[8];
            float4 f0 = __ldg((const float4*)&w[rw * 64 + c]);
            float4 f1 = __ldg((const float4*)&w[rw * 64 + c + 4]);
            o[0]=f0.x; o[1]=f0.y; o[2]=f0.z; o[3]=f0.w;
            o[4]=f1.x; o[5]=f1.y; o[6]=f1.z; o[7]=f1.w;
            uint4 h4, l4;
            split8(o, h4, l4);
            *(uint4*)(dH + c * 2) = h4;
            *(uint4*)(dL + c * 2) = l4;
        }
    }
    if (t < 192) qbias[t] = __ldg(&Bm[t >> 6][t & 63]);

    {
        const int r  = t >> 1;
        const int hf = (t & 1) * 32;
        const int gr = row0 + r;
        char* pH = qsm + QOFF_AH + r * RSTB;
        char* pL = qsm + QOFF_AL + r * RSTB;
        #pragma unroll
        for (int c8 = 0; c8 < 32; c8 += 8) {
            int c = hf + c8;
            float o[8] = {0,0,0,0,0,0,0,0};
            if (gr < n) {
                float4 f0 = __ldg((const float4*)&feat[gr * 64 + c]);
                float4 f1 = __ldg((const float4*)&feat[gr * 64 + c + 4]);
                o[0]=f0.x; o[1]=f0.y; o[2]=f0.z; o[3]=f0.w;
                o[4]=f1.x; o[5]=f1.y; o[6]=f1.z; o[7]=f1.w;
            }
            uint4 h4, l4;
            split8(o, h4, l4);
            *(uint4*)(pH + c * 2) = h4;
            *(uint4*)(pL + c * 2) = l4;
        }
    }
    __syncthreads();

    const int q  = lid >> 3;
    const int rl = lid & 7;
    uint32_t aoff[4];
    #pragma unroll
    for (int k = 0; k < 4; k++)
        aoff[k] = (uint32_t)(wid * 16 + rl + (q & 1) * 8) * RSTB
                + (uint32_t)(k * 32) + (uint32_t)((q >> 1) * 16);
    uint32_t Ah[4][4], Al[4][4];
    #pragma unroll
    for (int k = 0; k < 4; k++) {
        ldsm4(Ah[k], sbase + QOFF_AH + aoff[k]);
        ldsm4(Al[k], sbase + QOFF_AL + aoff[k]);
    }

    const int dr = lid >> 2;
    const int dc = (lid & 3) * 2;
    float* Om[3] = { g_q, g_k, g_v };
    float acc[8][4];

    #pragma unroll
    for (int m = 0; m < 3; m++) {
        gemm_frags(acc, Ah, Al, sbase + QOFF_W + m * 18432,
                   sbase + QOFF_W + m * 18432 + 9216, lid);
        const int grA = row0 + wid * 16 + dr;
        const int grB = grA + 8;
        #pragma unroll
        for (int nt = 0; nt < 8; nt++) {
            int c = nt * 8 + dc;
            float b0 = qbias[m * 64 + c], b1 = qbias[m * 64 + c + 1];
            if (grA < n) *(float2*)&Om[m][grA * 64 + c] = make_float2(acc[nt][0] + b0, acc[nt][1] + b1);
            if (grB < n) *(float2*)&Om[m][grB * 64 + c] = make_float2(acc[nt][2] + b0, acc[nt][3] + b1);
        }
    }
}

// ======================= kernel 2: bf16 HMMA fused kernel (256 thr) =========
// Zero block barriers in the main loop; epilogue = ONE batched 32x64x64 GEMM.
#define OFF_W1H  0
#define OFF_W1L  9216
#define OFF_W2H  18432
#define OFF_W2L  27648
#define OFF_WOH  36864
#define OFF_WOL  46080
#define OFF_AH   55296         // A tile hi; per-warp logits rows 0-7 overlay
#define OFF_AL   73728         // A tile lo; per-warp logits rows 8-15 overlay
#define OFF_SOH  92160         // s_o tile hi: 32 rows x RSTB = 4608
#define OFF_SOL  96768         // s_o tile lo
#define OFF_STAT 101376        // rx,ry,rz,mu,rs (5*512B) + nb (512B)
#define OFF_SV   104448        // 768 floats
#define SMEM_BYTES 107520

__global__ __launch_bounds__(256, 2) void fused_kernel(
    const float* __restrict__ points,
    const float* __restrict__ feat,
    const int*   __restrict__ nbr,
    const float* __restrict__ wp,  const float* __restrict__ bp,
    const float* __restrict__ gp,  const float* __restrict__ betap,
    const float* __restrict__ wg1, const float* __restrict__ bg1,
    const float* __restrict__ gg,  const float* __restrict__ betag,
    const float* __restrict__ wg2, const float* __restrict__ bg2,
    const float* __restrict__ wo,  const float* __restrict__ bo,
    float* __restrict__ outp, int n)
{
    extern __shared__ char smb[];
    float* s_rx = (float*)(smb + OFF_STAT);
    float* s_ry = s_rx + 128;
    float* s_rz = s_ry + 128;
    float* s_mu = s_rz + 128;
    float* s_rs = s_mu + 128;
    int*   s_nb = (int*)(s_rs + 128);
    float* sv   = (float*)(smb + OFF_SV);
    // sv: [0]=bg1 [64]=gg [128]=betag [192]=bg2 [256]=bp [320]=gp [384]=betap
    //     [448]=bo [512..704)=wp rows

    const int t   = threadIdx.x;
    const int wid = t >> 5;
    const int lid = t & 31;
    const uint32_t sbase = smem_u32(smb);

    if (t < 64) {
        sv[t]       = bg1[t];   sv[64 + t]  = gg[t];      sv[128 + t] = betag[t];
        sv[192 + t] = bg2[t];   sv[256 + t] = bp[t];      sv[320 + t] = gp[t];
        sv[384 + t] = betap[t]; sv[448 + t] = bo[t];
        sv[512 + t] = wp[t];    sv[576 + t] = wp[64 + t]; sv[640 + t] = wp[128 + t];
    }

    // ---- stage weights wg1/wg2/wo: bf16 hi/lo split ----
    {
        const float* Wm3[3] = { wg1, wg2, wo };
        for (int idx = t; idx < 384; idx += 256) {
            const int m  = idx / 128;
            const int rw = (idx & 127) >> 1;
            const int hf = (idx & 1) * 32;
            const float* w = Wm3[m];
            char* dH = smb + m * 18432 + rw * RSTB;   // W1H/W2H/WOH at m*18432
            char* dL = dH + 9216;
            #pragma unroll
            for (int c8 = 0; c8 < 32; c8 += 8) {
                int c = hf + c8;
                float o[8];
                float4 f0 = __ldg((const float4*)&w[rw * 64 + c]);
                float4 f1 = __ldg((const float4*)&w[rw * 64 + c + 4]);
                o[0]=f0.x; o[1]=f0.y; o[2]=f0.z; o[3]=f0.w;
                o[4]=f1.x; o[5]=f1.y; o[6]=f1.z; o[7]=f1.w;
                uint4 h4, l4;
                split8(o, h4, l4);
                *(uint4*)(dH + c * 2) = h4;
                *(uint4*)(dL + c * 2) = l4;
            }
        }
    }
    __syncthreads();   // weights/sv ready

    // fragment geometry: warp wid owns rows [wid*16, wid*16+16) = ONE point
    const int q  = lid >> 3;
    const int rl = lid & 7;
    uint32_t aoff[4];
    #pragma unroll
    for (int k = 0; k < 4; k++)
        aoff[k] = (uint32_t)(wid * 16 + rl + (q & 1) * 8) * RSTB
                + (uint32_t)(k * 32) + (uint32_t)((q >> 1) * 16);
    const int dr  = lid >> 2;
    const int dc  = (lid & 3) * 2;
    const int rtl = (lid >> 3) & 3;
    const int cg  = lid & 7;
    const int c0  = cg * 8;

    // phase-A row mapping (2 threads per row)
    const int rA  = t >> 1;
    const int haA = t & 1;
    const int jnA = rA & 15;
    const int rqA = rA >> 4;

    float acc[8][4];

    int nb_pref;
    {
        int np0  = blockIdx.x * PPB + rqA;
        int npc0 = (np0 < n) ? np0 : 0;
        nb_pref  = __ldg(&nbr[npc0 * 16 + jnA]);
    }

    for (int b = 0; b < 4; b++) {
        const int pbase = blockIdx.x * PPB + b * 8;

        // ---------------- phase A: 2 threads per row (32 ch each) -----------
        {
            const int r   = rA;
            const int ha  = haA;
            const int cb  = ha * 32;
            const int np  = pbase + rqA;
            const int npc = (np < n) ? np : 0;
            const int nb  = nb_pref;

            float rx = __ldg(&points[nb * 3 + 0]) - __ldg(&points[npc * 3 + 0]);
            float ry = __ldg(&points[nb * 3 + 1]) - __ldg(&points[npc * 3 + 1]);
            float rz = __ldg(&points[nb * 3 + 2]) - __ldg(&points[npc * 3 + 2]);

            if (b < 3) {
                int np1  = pbase + 8 + rqA;
                int npc1 = (np1 < n) ? np1 : 0;
                nb_pref  = __ldg(&nbr[npc1 * 16 + jnA]);
            }

            float pre[32];
            float s1 = 0.f, s2 = 0.f;
            #pragma unroll
            for (int cc = 0; cc < 32; cc++) {
                int c = cb + cc;
                float pr = fmaf(rx, sv[512 + c], fmaf(ry, sv[576 + c], fmaf(rz, sv[640 + c], sv[256 + c])));
                pre[cc] = pr;
                s1 += pr; s2 += pr * pr;
            }
            s1 += __shfl_xor_sync(0xffffffffu, s1, 1);
            s2 += __shfl_xor_sync(0xffffffffu, s2, 1);
            float mu = s1 * 0.015625f;
            float rs = rsqrtf(s2 * 0.015625f - mu * mu + EPS);
            if (ha == 0) {
                s_rx[r] = rx; s_ry[r] = ry; s_rz[r] = rz;
                s_mu[r] = mu; s_rs[r] = rs; s_nb[r] = nb;
            }

            const float* gkp = &g_k[(size_t)nb * 64];
            const float* qp  = &g_q[(size_t)npc * 64];
            char* pH = smb + OFF_AH + r * RSTB;
            char* pL = smb + OFF_AL + r * RSTB;
            #pragma unroll
            for (int g8 = 0; g8 < 32; g8 += 8) {
                int c8 = cb + g8;
                float4 qa = *(const float4*)&qp[c8];
                float4 qb = *(const float4*)&qp[c8 + 4];
                float4 ka = *(const float4*)&gkp[c8];
                float4 kb = *(const float4*)&gkp[c8 + 4];
                float o[8];
                #pragma unroll
                for (int u = 0; u < 8; u++) {
                    int c = c8 + u;
                    float p = fmaxf(fmaf((pre[g8 + u] - mu) * rs, sv[320 + c], sv[384 + c]), 0.f);
                    float qv = (u < 4) ? (&qa.x)[u] : (&qb.x)[u - 4];
                    float kv = (u < 4) ? (&ka.x)[u] : (&kb.x)[u - 4];
                    o[u] = qv - kv + p;
                }
                uint4 h4, l4;
                split8(o, h4, l4);
                *(uint4*)(pH + c8 * 2) = h4;
                *(uint4*)(pL + c8 * 2) = l4;
            }
        }
        __syncwarp();

        // ---------------- GEMM1 (A-frags from own rows) ---------------------
        uint32_t Ah[4][4], Al[4][4];
        #pragma unroll
        for (int k = 0; k < 4; k++) {
            ldsm4(Ah[k], sbase + OFF_AH + aoff[k]);
            ldsm4(Al[k], sbase + OFF_AL + aoff[k]);
        }
        gemm_frags(acc, Ah, Al, sbase + OFF_W1H, sbase + OFF_W1L, lid);

        // ---------------- bias + in-fragment LN + relu -> A2 fragments ------
        uint32_t A2h[4][4], A2l[4][4];
        {
            float va[16], vb[16];
            float s1a = 0.f, s2a = 0.f, s1b = 0.f, s2b = 0.f;
            #pragma unroll
            for (int nt = 0; nt < 8; nt++) {
                int c = nt * 8 + dc;
                float x0 = acc[nt][0] + sv[c];
                float x1 = acc[nt][1] + sv[c + 1];
                float y0 = acc[nt][2] + sv[c];
                float y1 = acc[nt][3] + sv[c + 1];
                va[nt * 2] = x0; va[nt * 2 + 1] = x1;
                vb[nt * 2] = y0; vb[nt * 2 + 1] = y1;
                s1a += x0 + x1; s2a += fmaf(x0, x0, x1 * x1);
                s1b += y0 + y1; s2b += fmaf(y0, y0, y1 * y1);
            }
            #pragma unroll
            for (int mk = 1; mk < 4; mk <<= 1) {
                s1a += __shfl_xor_sync(0xffffffffu, s1a, mk);
                s2a += __shfl_xor_sync(0xffffffffu, s2a, mk);
                s1b += __shfl_xor_sync(0xffffffffu, s1b, mk);
                s2b += __shfl_xor_sync(0xffffffffu, s2b, mk);
            }
            float mua = s1a * 0.015625f;
            float rsa = rsqrtf(s2a * 0.015625f - mua * mua + EPS);
            float mub = s1b * 0.015625f;
            float rsb = rsqrtf(s2b * 0.015625f - mub * mub + EPS);
            #pragma unroll
            for (int nt = 0; nt < 8; nt++) {
                int c = nt * 8 + dc;
                float g0 = sv[64 + c], g1 = sv[64 + c + 1];
                float e0 = sv[128 + c], e1 = sv[128 + c + 1];
                float h0 = fmaxf(fmaf((va[nt*2]   - mua) * rsa, g0, e0), 0.f);
                float h1 = fmaxf(fmaf((va[nt*2+1] - mua) * rsa, g1, e1), 0.f);
                float h2 = fmaxf(fmaf((vb[nt*2]   - mub) * rsb, g0, e0), 0.f);
                float h3 = fmaxf(fmaf((vb[nt*2+1] - mub) * rsb, g1, e1), 0.f);
                int kt = nt >> 1, hh = (nt & 1) * 2;
                split2(h0, h1, A2h[kt][hh],     A2l[kt][hh]);
                split2(h2, h3, A2h[kt][hh + 1], A2l[kt][hh + 1]);
            }
        }

        // ---------------- GEMM2 from register A-fragments -------------------
        gemm_frags(acc, A2h, A2l, sbase + OFF_W2H, sbase + OFF_W2L, lid);

        // ---------------- logits (+bg2) -> own per-warp chunks --------------
        {
            float* wrA = (float*)(smb + OFF_AH + wid * LCHB + dr * LRST);
            float* wrB = (float*)(smb + OFF_AL + wid * LCHB + dr * LRST);
            #pragma unroll
            for (int nt = 0; nt < 8; nt++) {
                int c = nt * 8 + dc;
                *(float2*)&wrA[c] = make_float2(acc[nt][0] + sv[192 + c], acc[nt][1] + sv[192 + c + 1]);
                *(float2*)&wrB[c] = make_float2(acc[nt][2] + sv[192 + c], acc[nt][3] + sv[192 + c + 1]);
            }
        }
        __syncwarp();

        // -------- softmax over neighbors + weighted sum (warp = point) ------
        {
            float lw[4][8];
            float4 gva[4], gvb[4];
            int rws[4];
            #pragma unroll
            for (int ii = 0; ii < 4; ii++) {
                int local = ii * 4 + rtl;
                int row = wid * 16 + local;
                rws[ii] = row;
                const float* wr = (const float*)(smb + (local < 8 ? OFF_AH : OFF_AL)
                                                 + wid * LCHB + (local & 7) * LRST);
                #pragma unroll
                for (int u = 0; u < 4; u++) {
                    float2 l2 = *(const float2*)&wr[c0 + 2 * u];
                    lw[ii][2 * u] = l2.x; lw[ii][2 * u + 1] = l2.y;
                }
                int nb2 = s_nb[row];
                gva[ii] = *(const float4*)&g_v[(size_t)nb2 * 64 + c0];
                gvb[ii] = *(const float4*)&g_v[(size_t)nb2 * 64 + c0 + 4];
            }
            float mx[8], se[8], wa[8], so[8];
            #pragma unroll
            for (int j = 0; j < 8; j++) {
                float m_ = fmaxf(fmaxf(lw[0][j], lw[1][j]), fmaxf(lw[2][j], lw[3][j]));
                m_ = fmaxf(m_, __shfl_xor_sync(0xffffffffu, m_, 8));
                m_ = fmaxf(m_, __shfl_xor_sync(0xffffffffu, m_, 16));
                mx[j] = m_; se[j] = 0.f; wa[j] = 0.f;
            }
            #pragma unroll
            for (int ii = 0; ii < 4; ii++) {
                int row = rws[ii];
                float rx = s_rx[row], ry = s_ry[row], rz = s_rz[row];
                float mu = s_mu[row], rs = s_rs[row];
                #pragma unroll
                for (int j = 0; j < 8; j++) {
                    int c = c0 + j;
                    float pre = fmaf(rx, sv[512 + c], fmaf(ry, sv[576 + c], fmaf(rz, sv[640 + c], sv[256 + c])));
                    float p = fmaxf(fmaf((pre - mu) * rs, sv[320 + c], sv[384 + c]), 0.f);
                    float gvv = (j < 4) ? (&gva[ii].x)[j] : (&gvb[ii].x)[j - 4];
                    float e = __expf(lw[ii][j] - mx[j]);
                    se[j] += e;
                    wa[j] = fmaf(e, gvv + p, wa[j]);
                }
            }
            #pragma unroll
            for (int j = 0; j < 8; j++) {
                se[j] += __shfl_xor_sync(0xffffffffu, se[j], 8);
                se[j] += __shfl_xor_sync(0xffffffffu, se[j], 16);
                wa[j] += __shfl_xor_sync(0xffffffffu, wa[j], 8);
                wa[j] += __shfl_xor_sync(0xffffffffu, wa[j], 16);
                so[j] = wa[j] / se[j];
            }
            // rtl==0 lanes (lid 0..7) cover all 64 channels: write s_o row
            if (rtl == 0) {
                int row = b * 8 + wid;
                uint4 h4, l4;
                split8(so, h4, l4);
                *(uint4*)(smb + OFF_SOH + row * RSTB + c0 * 2) = h4;
                *(uint4*)(smb + OFF_SOL + row * RSTB + c0 * 2) = l4;
            }
        }
        // no block barrier between sub-batches
    }

    // ---------------- batched epilogue: out(32x64) = s_o @ wo + bo + res ----
    __syncthreads();
    if (wid < 2) {
        uint32_t aoffE[4];
        #pragma unroll
        for (int k = 0; k < 4; k++)
            aoffE[k] = (uint32_t)(wid * 16 + rl + (q & 1) * 8) * RSTB
                     + (uint32_t)(k * 32) + (uint32_t)((q >> 1) * 16);
        uint32_t AhE[4][4], AlE[4][4];
        #pragma unroll
        for (int k = 0; k < 4; k++) {
            ldsm4(AhE[k], sbase + OFF_SOH + aoffE[k]);
            ldsm4(AlE[k], sbase + OFF_SOL + aoffE[k]);
        }
        gemm_frags(acc, AhE, AlE, sbase + OFF_WOH, sbase + OFF_WOL, lid);
        const int rEA = wid * 16 + dr;
        const int rEB = rEA + 8;
        const int pA = blockIdx.x * PPB + rEA;
        const int pB = blockIdx.x * PPB + rEB;
        #pragma unroll
        for (int nt = 0; nt < 8; nt++) {
            int c = nt * 8 + dc;
            float b0 = sv[448 + c], b1 = sv[448 + c + 1];
            if (pA < n) {
                float2 f2 = __ldg((const float2*)&feat[pA * 64 + c]);
                *(float2*)&outp[pA * 64 + c] =
                    make_float2(acc[nt][0] + b0 + f2.x, acc[nt][1] + b1 + f2.y);
            }
            if (pB < n) {
                float2 f2 = __ldg((const float2*)&feat[pB * 64 + c]);
                *(float2*)&outp[pB * 64 + c] =
                    make_float2(acc[nt][2] + b0 + f2.x, acc[nt][3] + b1 + f2.y);
            }
        }
    }
}

// ======================= launch =============================================
extern "C" void kernel_launch(void* const* d_in, const int* in_sizes, int n_in,
                              void* d_out, int out_size)
{
    const float* points = (const float*)d_in[0];
    const float* feat   = (const float*)d_in[1];
    const int*   nbr    = (const int*)  d_in[2];
    const float* wq = (const float*)d_in[3];
    const float* bq = (const float*)d_in[4];
    const float* wk = (const float*)d_in[5];
    const float* bk = (const float*)d_in[6];
    const float* wv = (const float*)d_in[7];
    const float* bv = (const float*)d_in[8];
    const float* wp = (const float*)d_in[9];
    const float* bp = (const float*)d_in[10];
    const float* gp = (const float*)d_in[11];
    const float* betap = (const float*)d_in[12];
    const float* wg1 = (const float*)d_in[13];
    const float* bg1 = (const float*)d_in[14];
    const float* gg  = (const float*)d_in[15];
    const float* betag = (const float*)d_in[16];
    const float* wg2 = (const float*)d_in[17];
    const float* bg2 = (const float*)d_in[18];
    const float* wo  = (const float*)d_in[19];
    const float* bo  = (const float*)d_in[20];
    float* outp = (float*)d_out;

    int n = in_sizes[1] / 64;
    if (n > NMAX) n = NMAX;

    cudaFuncSetAttribute(qkv_kernel, cudaFuncAttributeMaxDynamicSharedMemorySize, QSMEM_BYTES);
    qkv_kernel<<<(n + 127) / 128, 256, QSMEM_BYTES>>>(feat, wq, bq, wk, bk, wv, bv, n);

    cudaFuncSetAttribute(fused_kernel, cudaFuncAttributeMaxDynamicSharedMemorySize, SMEM_BYTES);
    fused_kernel<<<(n + PPB - 1) / PPB, 256, SMEM_BYTES>>>(
        points, feat, nbr,
        wp, bp, gp, betap,
        wg1, bg1, gg, betag,
        wg2, bg2, wo, bo,
        outp, n);
}

// round 15
// speedup vs baseline: 1.5248x; 1.5248x over previous
#include <cuda_runtime.h>
#include <cuda_bf16.h>
#include <cstdint>

#define NMAX 50000
#define EPS  1e-5f
#define PPB  32          // points per block (4 sub-batches of 8)
#define RSTB 144         // bf16 tile row stride in BYTES (64 bf16 data + pad)
#define LCHB 2304        // per-warp logits chunk bytes (== 16 A rows)
#define LRST 272         // logits row stride bytes (68 floats)

// ---------------- scratch (static device arrays: allocation-free) ----------
__device__ float g_q[NMAX * 64];
__device__ float g_k[NMAX * 64];
__device__ float g_v[NMAX * 64];

// ---------------- mma / ldmatrix helpers ------------------------------------
__device__ __forceinline__ uint32_t smem_u32(const void* p) {
    uint32_t a;
    asm("{ .reg .u64 t; cvta.to.shared.u64 t, %1; cvt.u32.u64 %0, t; }" : "=r"(a) : "l"(p));
    return a;
}
__device__ __forceinline__ void ldsm4(uint32_t* r, uint32_t addr) {
    asm volatile("ldmatrix.sync.aligned.m8n8.x4.shared.b16 {%0,%1,%2,%3},[%4];"
        : "=r"(r[0]), "=r"(r[1]), "=r"(r[2]), "=r"(r[3]) : "r"(addr));
}
__device__ __forceinline__ void ldsm4t(uint32_t* r, uint32_t addr) {
    asm volatile("ldmatrix.sync.aligned.m8n8.x4.trans.shared.b16 {%0,%1,%2,%3},[%4];"
        : "=r"(r[0]), "=r"(r[1]), "=r"(r[2]), "=r"(r[3]) : "r"(addr));
}
__device__ __forceinline__ void mma_bf16(float* c, const uint32_t* a, const uint32_t* b) {
    asm volatile("mma.sync.aligned.m16n8k16.row.col.f32.bf16.bf16.f32 "
        "{%0,%1,%2,%3},{%4,%5,%6,%7},{%8,%9},{%0,%1,%2,%3};"
        : "+f"(c[0]), "+f"(c[1]), "+f"(c[2]), "+f"(c[3])
        : "r"(a[0]), "r"(a[1]), "r"(a[2]), "r"(a[3]), "r"(b[0]), "r"(b[1]));
}
__device__ __forceinline__ void split2(float x0, float x1, uint32_t& hi, uint32_t& lo) {
    __nv_bfloat162 h = __floats2bfloat162_rn(x0, x1);
    hi = *(uint32_t*)&h;
    __nv_bfloat162 l = __floats2bfloat162_rn(x0 - __bfloat162float(h.x),
                                             x1 - __bfloat162float(h.y));
    lo = *(uint32_t*)&l;
}
__device__ __forceinline__ void split8(const float* o, uint4& h4, uint4& l4) {
    split2(o[0], o[1], h4.x, l4.x);
    split2(o[2], o[3], h4.y, l4.y);
    split2(o[4], o[5], h4.z, l4.z);
    split2(o[6], o[7], h4.w, l4.w);
}

// GEMM core: acc(16x64 per warp) = Ahi*Bhi + Alo*Bhi + Ahi*Blo
__device__ __forceinline__ void gemm_frags(
    float acc[8][4], const uint32_t Ah[4][4], const uint32_t Al[4][4],
    uint32_t wbaseH, uint32_t wbaseL, int lid)
{
    #pragma unroll
    for (int nt = 0; nt < 8; nt++)
        #pragma unroll
        for (int i = 0; i < 4; i++) acc[nt][i] = 0.f;
    const uint32_t colb = (uint32_t)(lid & 15) * RSTB + (uint32_t)(lid >> 4) * 16;
    #pragma unroll
    for (int p = 0; p < 4; p++) {
        const uint32_t cofs = colb + (uint32_t)(p * 32);
        uint32_t bh[4][4], bl[4][4];
        #pragma unroll
        for (int k = 0; k < 4; k++) ldsm4t(bh[k], wbaseH + (uint32_t)(k * 16) * RSTB + cofs);
        #pragma unroll
        for (int k = 0; k < 4; k++) { mma_bf16(acc[2*p], Ah[k], &bh[k][0]); mma_bf16(acc[2*p+1], Ah[k], &bh[k][2]); }
        #pragma unroll
        for (int k = 0; k < 4; k++) ldsm4t(bl[k], wbaseL + (uint32_t)(k * 16) * RSTB + cofs);
        #pragma unroll
        for (int k = 0; k < 4; k++) { mma_bf16(acc[2*p], Al[k], &bh[k][0]); mma_bf16(acc[2*p+1], Al[k], &bh[k][2]); }
        #pragma unroll
        for (int k = 0; k < 4; k++) { mma_bf16(acc[2*p], Ah[k], &bl[k][0]); mma_bf16(acc[2*p+1], Ah[k], &bl[k][2]); }
    }
}

// ======================= kernel 1: q/k/v projections (HMMA) =================
#define QOFF_W    0              // 3 x (hi 9216 + lo 9216) = 55296
#define QOFF_AH   55296
#define QOFF_AL   73728
#define QOFF_BIAS 92160          // 192 floats
#define QSMEM_BYTES 92928

__global__ __launch_bounds__(256, 2) void qkv_kernel(
    const float* __restrict__ feat,
    const float* __restrict__ wq, const float* __restrict__ bq,
    const float* __restrict__ wk, const float* __restrict__ bk,
    const float* __restrict__ wv, const float* __restrict__ bv,
    int n)
{
    extern __shared__ char qsm[];
    float* qbias = (float*)(qsm + QOFF_BIAS);
    const int t   = threadIdx.x;
    const int wid = t >> 5;
    const int lid = t & 31;
    const int row0 = blockIdx.x * 128;
    const uint32_t sbase = smem_u32(qsm);

    const float* Wm[3] = { wq, wk, wv };
    const float* Bm[3] = { bq, bk, bv };

    for (int idx = t; idx < 384; idx += 256) {
        const int m  = idx / 128;
        const int rw = (idx & 127) >> 1;
        const int hf = (idx & 1) * 32;
        const float* w = Wm[m];
        char* dH = qsm + QOFF_W + m * 18432 + rw * RSTB;
        char* dL = dH + 9216;
        #pragma unroll
        for (int c8 = 0; c8 < 32; c8 += 8) {
            int c = hf + c8;
            float o[8];
            float4 f0 = __ldg((const float4*)&w[rw * 64 + c]);
            float4 f1 = __ldg((const float4*)&w[rw * 64 + c + 4]);
            o[0]=f0.x; o[1]=f0.y; o[2]=f0.z; o[3]=f0.w;
            o[4]=f1.x; o[5]=f1.y; o[6]=f1.z; o[7]=f1.w;
            uint4 h4, l4;
            split8(o, h4, l4);
            *(uint4*)(dH + c * 2) = h4;
            *(uint4*)(dL + c * 2) = l4;
        }
    }
    if (t < 192) qbias[t] = __ldg(&Bm[t >> 6][t & 63]);

    {
        const int r  = t >> 1;
        const int hf = (t & 1) * 32;
        const int gr = row0 + r;
        char* pH = qsm + QOFF_AH + r * RSTB;
        char* pL = qsm + QOFF_AL + r * RSTB;
        #pragma unroll
        for (int c8 = 0; c8 < 32; c8 += 8) {
            int c = hf + c8;
            float o[8] = {0,0,0,0,0,0,0,0};
            if (gr < n) {
                float4 f0 = __ldg((const float4*)&feat[gr * 64 + c]);
                float4 f1 = __ldg((const float4*)&feat[gr * 64 + c + 4]);
                o[0]=f0.x; o[1]=f0.y; o[2]=f0.z; o[3]=f0.w;
                o[4]=f1.x; o[5]=f1.y; o[6]=f1.z; o[7]=f1.w;
            }
            uint4 h4, l4;
            split8(o, h4, l4);
            *(uint4*)(pH + c * 2) = h4;
            *(uint4*)(pL + c * 2) = l4;
        }
    }
    __syncthreads();

    const int q  = lid >> 3;
    const int rl = lid & 7;
    uint32_t aoff[4];
    #pragma unroll
    for (int k = 0; k < 4; k++)
        aoff[k] = (uint32_t)(wid * 16 + rl + (q & 1) * 8) * RSTB
                + (uint32_t)(k * 32) + (uint32_t)((q >> 1) * 16);
    uint32_t Ah[4][4], Al[4][4];
    #pragma unroll
    for (int k = 0; k < 4; k++) {
        ldsm4(Ah[k], sbase + QOFF_AH + aoff[k]);
        ldsm4(Al[k], sbase + QOFF_AL + aoff[k]);
    }

    const int dr = lid >> 2;
    const int dc = (lid & 3) * 2;
    float* Om[3] = { g_q, g_k, g_v };
    float acc[8][4];

    #pragma unroll
    for (int m = 0; m < 3; m++) {
        gemm_frags(acc, Ah, Al, sbase + QOFF_W + m * 18432,
                   sbase + QOFF_W + m * 18432 + 9216, lid);
        const int grA = row0 + wid * 16 + dr;
        const int grB = grA + 8;
        #pragma unroll
        for (int nt = 0; nt < 8; nt++) {
            int c = nt * 8 + dc;
            float b0 = qbias[m * 64 + c], b1 = qbias[m * 64 + c + 1];
            if (grA < n) *(float2*)&Om[m][grA * 64 + c] = make_float2(acc[nt][0] + b0, acc[nt][1] + b1);
            if (grB < n) *(float2*)&Om[m][grB * 64 + c] = make_float2(acc[nt][2] + b0, acc[nt][3] + b1);
        }
    }
}

// ======================= kernel 2: bf16 HMMA fused kernel (256 thr) =========
// Zero block barriers in the main loop (R11 structure). Epilogue DEFERRED:
// each warp spills its per-sub-batch s_o rows (fp32) to a warp-private slot,
// then after the loop projects all 4 of its points reading wos ONCE.
#define OFF_W1H  0
#define OFF_W1L  9216
#define OFF_W2H  18432
#define OFF_W2L  27648
#define OFF_AH   36864         // A tile hi; per-warp logits rows 0-7 overlay
#define OFF_AL   55296         // A tile lo; per-warp logits rows 8-15 overlay
#define OFF_STAT 73728         // rx,ry,rz,mu,rs (5*512B) + nb (512B)
#define OFF_SV   76800         // 768 floats
#define OFF_WO   79872         // wo staged fp32: 16384 bytes
#define OFF_SOF  96256         // s_o fp32: 8 warps x 4 sub-batches x 64 = 8192B
#define SMEM_BYTES 104448

__global__ __launch_bounds__(256, 2) void fused_kernel(
    const float* __restrict__ points,
    const float* __restrict__ feat,
    const int*   __restrict__ nbr,
    const float* __restrict__ wp,  const float* __restrict__ bp,
    const float* __restrict__ gp,  const float* __restrict__ betap,
    const float* __restrict__ wg1, const float* __restrict__ bg1,
    const float* __restrict__ gg,  const float* __restrict__ betag,
    const float* __restrict__ wg2, const float* __restrict__ bg2,
    const float* __restrict__ wo,  const float* __restrict__ bo,
    float* __restrict__ outp, int n)
{
    extern __shared__ char smb[];
    float* s_rx = (float*)(smb + OFF_STAT);
    float* s_ry = s_rx + 128;
    float* s_rz = s_ry + 128;
    float* s_mu = s_rz + 128;
    float* s_rs = s_mu + 128;
    int*   s_nb = (int*)(s_rs + 128);
    float* sv   = (float*)(smb + OFF_SV);
    float* wos  = (float*)(smb + OFF_WO);
    float* s_of = (float*)(smb + OFF_SOF);
    // sv: [0]=bg1 [64]=gg [128]=betag [192]=bg2 [256]=bp [320]=gp [384]=betap
    //     [448]=bo [512..704)=wp rows

    const int t   = threadIdx.x;
    const int wid = t >> 5;
    const int lid = t & 31;
    const uint32_t sbase = smem_u32(smb);

    if (t < 64) {
        sv[t]       = bg1[t];   sv[64 + t]  = gg[t];      sv[128 + t] = betag[t];
        sv[192 + t] = bg2[t];   sv[256 + t] = bp[t];      sv[320 + t] = gp[t];
        sv[384 + t] = betap[t]; sv[448 + t] = bo[t];
        sv[512 + t] = wp[t];    sv[576 + t] = wp[64 + t]; sv[640 + t] = wp[128 + t];
    }
    for (int i = t; i < 1024; i += 256)
        ((float4*)wos)[i] = __ldg(&((const float4*)wo)[i]);

    // ---- stage weights: bf16 hi/lo split, row-major [k][n], stride RSTB ----
    {
        const int rw  = t & 63;
        const int sel = t >> 6;
        const int m   = sel >> 1;
        const int hf  = (sel & 1) * 32;
        const float* w = m ? wg2 : wg1;
        char* dH = smb + (m ? OFF_W2H : OFF_W1H) + rw * RSTB;
        char* dL = smb + (m ? OFF_W2L : OFF_W1L) + rw * RSTB;
        #pragma unroll
        for (int c8 = 0; c8 < 32; c8 += 8) {
            int c = hf + c8;
            float o[8];
            float4 f0 = __ldg((const float4*)&w[rw * 64 + c]);
            float4 f1 = __ldg((const float4*)&w[rw * 64 + c + 4]);
            o[0]=f0.x; o[1]=f0.y; o[2]=f0.z; o[3]=f0.w;
            o[4]=f1.x; o[5]=f1.y; o[6]=f1.z; o[7]=f1.w;
            uint4 h4, l4;
            split8(o, h4, l4);
            *(uint4*)(dH + c * 2) = h4;
            *(uint4*)(dL + c * 2) = l4;
        }
    }
    __syncthreads();   // weights/sv/wos ready; ONLY block barrier in kernel

    // fragment geometry: warp wid owns rows [wid*16, wid*16+16) = ONE point
    const int q  = lid >> 3;
    const int rl = lid & 7;
    uint32_t aoff[4];
    #pragma unroll
    for (int k = 0; k < 4; k++)
        aoff[k] = (uint32_t)(wid * 16 + rl + (q & 1) * 8) * RSTB
                + (uint32_t)(k * 32) + (uint32_t)((q >> 1) * 16);
    const int dr  = lid >> 2;
    const int dc  = (lid & 3) * 2;
    const int rtl = (lid >> 3) & 3;
    const int cg  = lid & 7;
    const int c0  = cg * 8;

    // phase-A row mapping (2 threads per row)
    const int rA  = t >> 1;
    const int haA = t & 1;
    const int jnA = rA & 15;
    const int rqA = rA >> 4;

    float acc[8][4];

    int nb_pref;
    {
        int np0  = blockIdx.x * PPB + rqA;
        int npc0 = (np0 < n) ? np0 : 0;
        nb_pref  = __ldg(&nbr[npc0 * 16 + jnA]);
    }

    for (int b = 0; b < 4; b++) {
        const int pbase = blockIdx.x * PPB + b * 8;

        // ---------------- phase A: 2 threads per row (32 ch each) -----------
        {
            const int r   = rA;
            const int ha  = haA;
            const int cb  = ha * 32;
            const int np  = pbase + rqA;
            const int npc = (np < n) ? np : 0;
            const int nb  = nb_pref;

            float rx = __ldg(&points[nb * 3 + 0]) - __ldg(&points[npc * 3 + 0]);
            float ry = __ldg(&points[nb * 3 + 1]) - __ldg(&points[npc * 3 + 1]);
            float rz = __ldg(&points[nb * 3 + 2]) - __ldg(&points[npc * 3 + 2]);

            if (b < 3) {
                int np1  = pbase + 8 + rqA;
                int npc1 = (np1 < n) ? np1 : 0;
                nb_pref  = __ldg(&nbr[npc1 * 16 + jnA]);
            }

            float pre[32];
            float s1 = 0.f, s2 = 0.f;
            #pragma unroll
            for (int cc = 0; cc < 32; cc++) {
                int c = cb + cc;
                float pr = fmaf(rx, sv[512 + c], fmaf(ry, sv[576 + c], fmaf(rz, sv[640 + c], sv[256 + c])));
                pre[cc] = pr;
                s1 += pr; s2 += pr * pr;
            }
            s1 += __shfl_xor_sync(0xffffffffu, s1, 1);
            s2 += __shfl_xor_sync(0xffffffffu, s2, 1);
            float mu = s1 * 0.015625f;
            float rs = rsqrtf(s2 * 0.015625f - mu * mu + EPS);
            if (ha == 0) {
                s_rx[r] = rx; s_ry[r] = ry; s_rz[r] = rz;
                s_mu[r] = mu; s_rs[r] = rs; s_nb[r] = nb;
            }

            const float* gkp = &g_k[(size_t)nb * 64];
            const float* qp  = &g_q[(size_t)npc * 64];
            char* pH = smb + OFF_AH + r * RSTB;
            char* pL = smb + OFF_AL + r * RSTB;
            #pragma unroll
            for (int g8 = 0; g8 < 32; g8 += 8) {
                int c8 = cb + g8;
                float4 qa = *(const float4*)&qp[c8];
                float4 qb = *(const float4*)&qp[c8 + 4];
                float4 ka = *(const float4*)&gkp[c8];
                float4 kb = *(const float4*)&gkp[c8 + 4];
                float o[8];
                #pragma unroll
                for (int u = 0; u < 8; u++) {
                    int c = c8 + u;
                    float p = fmaxf(fmaf((pre[g8 + u] - mu) * rs, sv[320 + c], sv[384 + c]), 0.f);
                    float qv = (u < 4) ? (&qa.x)[u] : (&qb.x)[u - 4];
                    float kv = (u < 4) ? (&ka.x)[u] : (&kb.x)[u - 4];
                    o[u] = qv - kv + p;
                }
                uint4 h4, l4;
                split8(o, h4, l4);
                *(uint4*)(pH + c8 * 2) = h4;
                *(uint4*)(pL + c8 * 2) = l4;
            }
        }
        __syncwarp();

        // ---------------- GEMM1 (A-frags from own rows) ---------------------
        uint32_t Ah[4][4], Al[4][4];
        #pragma unroll
        for (int k = 0; k < 4; k++) {
            ldsm4(Ah[k], sbase + OFF_AH + aoff[k]);
            ldsm4(Al[k], sbase + OFF_AL + aoff[k]);
        }
        gemm_frags(acc, Ah, Al, sbase + OFF_W1H, sbase + OFF_W1L, lid);

        // ---------------- bias + in-fragment LN + relu -> A2 fragments ------
        uint32_t A2h[4][4], A2l[4][4];
        {
            float va[16], vb[16];
            float s1a = 0.f, s2a = 0.f, s1b = 0.f, s2b = 0.f;
            #pragma unroll
            for (int nt = 0; nt < 8; nt++) {
                int c = nt * 8 + dc;
                float x0 = acc[nt][0] + sv[c];
                float x1 = acc[nt][1] + sv[c + 1];
                float y0 = acc[nt][2] + sv[c];
                float y1 = acc[nt][3] + sv[c + 1];
                va[nt * 2] = x0; va[nt * 2 + 1] = x1;
                vb[nt * 2] = y0; vb[nt * 2 + 1] = y1;
                s1a += x0 + x1; s2a += fmaf(x0, x0, x1 * x1);
                s1b += y0 + y1; s2b += fmaf(y0, y0, y1 * y1);
            }
            #pragma unroll
            for (int mk = 1; mk < 4; mk <<= 1) {
                s1a += __shfl_xor_sync(0xffffffffu, s1a, mk);
                s2a += __shfl_xor_sync(0xffffffffu, s2a, mk);
                s1b += __shfl_xor_sync(0xffffffffu, s1b, mk);
                s2b += __shfl_xor_sync(0xffffffffu, s2b, mk);
            }
            float mua = s1a * 0.015625f;
            float rsa = rsqrtf(s2a * 0.015625f - mua * mua + EPS);
            float mub = s1b * 0.015625f;
            float rsb = rsqrtf(s2b * 0.015625f - mub * mub + EPS);
            #pragma unroll
            for (int nt = 0; nt < 8; nt++) {
                int c = nt * 8 + dc;
                float g0 = sv[64 + c], g1 = sv[64 + c + 1];
                float e0 = sv[128 + c], e1 = sv[128 + c + 1];
                float h0 = fmaxf(fmaf((va[nt*2]   - mua) * rsa, g0, e0), 0.f);
                float h1 = fmaxf(fmaf((va[nt*2+1] - mua) * rsa, g1, e1), 0.f);
                float h2 = fmaxf(fmaf((vb[nt*2]   - mub) * rsb, g0, e0), 0.f);
                float h3 = fmaxf(fmaf((vb[nt*2+1] - mub) * rsb, g1, e1), 0.f);
                int kt = nt >> 1, hh = (nt & 1) * 2;
                split2(h0, h1, A2h[kt][hh],     A2l[kt][hh]);
                split2(h2, h3, A2h[kt][hh + 1], A2l[kt][hh + 1]);
            }
        }

        // ---------------- GEMM2 from register A-fragments -------------------
        gemm_frags(acc, A2h, A2l, sbase + OFF_W2H, sbase + OFF_W2L, lid);

        // ---------------- logits (+bg2) -> own per-warp chunks --------------
        {
            float* wrA = (float*)(smb + OFF_AH + wid * LCHB + dr * LRST);
            float* wrB = (float*)(smb + OFF_AL + wid * LCHB + dr * LRST);
            #pragma unroll
            for (int nt = 0; nt < 8; nt++) {
                int c = nt * 8 + dc;
                *(float2*)&wrA[c] = make_float2(acc[nt][0] + sv[192 + c], acc[nt][1] + sv[192 + c + 1]);
                *(float2*)&wrB[c] = make_float2(acc[nt][2] + sv[192 + c], acc[nt][3] + sv[192 + c + 1]);
            }
        }
        __syncwarp();

        // -------- softmax over neighbors + weighted sum (warp = point) ------
        {
            float lw[4][8];
            float4 gva[4], gvb[4];
            int rws[4];
            #pragma unroll
            for (int ii = 0; ii < 4; ii++) {
                int local = ii * 4 + rtl;
                int row = wid * 16 + local;
                rws[ii] = row;
                const float* wr = (const float*)(smb + (local < 8 ? OFF_AH : OFF_AL)
                                                 + wid * LCHB + (local & 7) * LRST);
                #pragma unroll
                for (int u = 0; u < 4; u++) {
                    float2 l2 = *(const float2*)&wr[c0 + 2 * u];
                    lw[ii][2 * u] = l2.x; lw[ii][2 * u + 1] = l2.y;
                }
                int nb2 = s_nb[row];
                gva[ii] = *(const float4*)&g_v[(size_t)nb2 * 64 + c0];
                gvb[ii] = *(const float4*)&g_v[(size_t)nb2 * 64 + c0 + 4];
            }
            float mx[8], se[8], wa[8], so[8];
            #pragma unroll
            for (int j = 0; j < 8; j++) {
                float m_ = fmaxf(fmaxf(lw[0][j], lw[1][j]), fmaxf(lw[2][j], lw[3][j]));
                m_ = fmaxf(m_, __shfl_xor_sync(0xffffffffu, m_, 8));
                m_ = fmaxf(m_, __shfl_xor_sync(0xffffffffu, m_, 16));
                mx[j] = m_; se[j] = 0.f; wa[j] = 0.f;
            }
            #pragma unroll
            for (int ii = 0; ii < 4; ii++) {
                int row = rws[ii];
                float rx = s_rx[row], ry = s_ry[row], rz = s_rz[row];
                float mu = s_mu[row], rs = s_rs[row];
                #pragma unroll
                for (int j = 0; j < 8; j++) {
                    int c = c0 + j;
                    float pre = fmaf(rx, sv[512 + c], fmaf(ry, sv[576 + c], fmaf(rz, sv[640 + c], sv[256 + c])));
                    float p = fmaxf(fmaf((pre - mu) * rs, sv[320 + c], sv[384 + c]), 0.f);
                    float gvv = (j < 4) ? (&gva[ii].x)[j] : (&gvb[ii].x)[j - 4];
                    float e = __expf(lw[ii][j] - mx[j]);
                    se[j] += e;
                    wa[j] = fmaf(e, gvv + p, wa[j]);
                }
            }
            #pragma unroll
            for (int j = 0; j < 8; j++) {
                se[j] += __shfl_xor_sync(0xffffffffu, se[j], 8);
                se[j] += __shfl_xor_sync(0xffffffffu, se[j], 16);
                wa[j] += __shfl_xor_sync(0xffffffffu, wa[j], 8);
                wa[j] += __shfl_xor_sync(0xffffffffu, wa[j], 16);
                so[j] = wa[j] / se[j];
            }
            // lanes rtl==0 (lid 0..7) cover all 64 channels: spill fp32 s_o row
            if (rtl == 0) {
                float* dst = &s_of[wid * 256 + b * 64 + c0];
                *(float4*)dst       = make_float4(so[0], so[1], so[2], so[3]);
                *(float4*)(dst + 4) = make_float4(so[4], so[5], so[6], so[7]);
            }
        }
        // no block barrier between sub-batches (all state warp-private)
    }

    // ---------------- deferred per-warp epilogue: 4 points, wo read ONCE ----
    __syncwarp();
    {
        const int pbase0 = blockIdx.x * PPB + wid;  // points pbase0 + 8*p
        float a0[4], a1[4];
        #pragma unroll
        for (int p = 0; p < 4; p++) {
            a0[p] = sv[448 + lid];
            a1[p] = sv[448 + lid + 32];
        }
        const float* sw = &s_of[wid * 256];
        #pragma unroll 4
        for (int k4 = 0; k4 < 64; k4 += 4) {
            float4 s4[4];
            #pragma unroll
            for (int p = 0; p < 4; p++) s4[p] = *(const float4*)&sw[p * 64 + k4];
            #pragma unroll
            for (int ku = 0; ku < 4; ku++) {
                int k = k4 + ku;
                float w0 = wos[k * 64 + lid];
                float w1 = wos[k * 64 + lid + 32];
                #pragma unroll
                for (int p = 0; p < 4; p++) {
                    float s_ = (&s4[p].x)[ku];
                    a0[p] = fmaf(s_, w0, a0[p]);
                    a1[p] = fmaf(s_, w1, a1[p]);
                }
            }
        }
        #pragma unroll
        for (int p = 0; p < 4; p++) {
            int pt = pbase0 + p * 8;
            if (pt < n) {
                outp[pt * 64 + lid]      = a0[p] + __ldg(&feat[pt * 64 + lid]);
                outp[pt * 64 + lid + 32] = a1[p] + __ldg(&feat[pt * 64 + lid + 32]);
            }
        }
    }
}

// ======================= launch =============================================
extern "C" void kernel_launch(void* const* d_in, const int* in_sizes, int n_in,
                              void* d_out, int out_size)
{
    const float* points = (const float*)d_in[0];
    const float* feat   = (const float*)d_in[1];
    const int*   nbr    = (const int*)  d_in[2];
    const float* wq = (const float*)d_in[3];
    const float* bq = (const float*)d_in[4];
    const float* wk = (const float*)d_in[5];
    const float* bk = (const float*)d_in[6];
    const float* wv = (const float*)d_in[7];
    const float* bv = (const float*)d_in[8];
    const float* wp = (const float*)d_in[9];
    const float* bp = (const float*)d_in[10];
    const float* gp = (const float*)d_in[11];
    const float* betap = (const float*)d_in[12];
    const float* wg1 = (const float*)d_in[13];
    const float* bg1 = (const float*)d_in[14];
    const float* gg  = (const float*)d_in[15];
    const float* betag = (const float*)d_in[16];
    const float* wg2 = (const float*)d_in[17];
    const float* bg2 = (const float*)d_in[18];
    const float* wo  = (const float*)d_in[19];
    const float* bo  = (const float*)d_in[20];
    float* outp = (float*)d_out;

    int n = in_sizes[1] / 64;
    if (n > NMAX) n = NMAX;

    cudaFuncSetAttribute(qkv_kernel, cudaFuncAttributeMaxDynamicSharedMemorySize, QSMEM_BYTES);
    qkv_kernel<<<(n + 127) / 128, 256, QSMEM_BYTES>>>(feat, wq, bq, wk, bk, wv, bv, n);

    cudaFuncSetAttribute(fused_kernel, cudaFuncAttributeMaxDynamicSharedMemorySize, SMEM_BYTES);
    fused_kernel<<<(n + PPB - 1) / PPB, 256, SMEM_BYTES>>>(
        points, feat, nbr,
        wp, bp, gp, betap,
        wg1, bg1, gg, betag,
        wg2, bg2, wo, bo,
        outp, n);
}

// round 16
// speedup vs baseline: 1.8251x; 1.1970x over previous
#include <cuda_runtime.h>
#include <cuda_bf16.h>
#include <cstdint>

#define NMAX 50000
#define EPS  1e-5f
#define PPB  32          // points per block (4 sub-batches of 8)
#define RSTB 144         // bf16 tile row stride in BYTES (64 bf16 data + pad)
#define LCHB 2304        // per-warp logits chunk bytes (== 16 A rows)
#define LRST 272         // logits row stride bytes (68 floats)

// ---------------- scratch (static device arrays: allocation-free) ----------
__device__ float g_q[NMAX * 64];
__device__ float g_k[NMAX * 64];
__device__ float g_v[NMAX * 64];

// ---------------- mma / ldmatrix helpers ------------------------------------
__device__ __forceinline__ uint32_t smem_u32(const void* p) {
    uint32_t a;
    asm("{ .reg .u64 t; cvta.to.shared.u64 t, %1; cvt.u32.u64 %0, t; }" : "=r"(a) : "l"(p));
    return a;
}
__device__ __forceinline__ void ldsm4(uint32_t* r, uint32_t addr) {
    asm volatile("ldmatrix.sync.aligned.m8n8.x4.shared.b16 {%0,%1,%2,%3},[%4];"
        : "=r"(r[0]), "=r"(r[1]), "=r"(r[2]), "=r"(r[3]) : "r"(addr));
}
__device__ __forceinline__ void ldsm4t(uint32_t* r, uint32_t addr) {
    asm volatile("ldmatrix.sync.aligned.m8n8.x4.trans.shared.b16 {%0,%1,%2,%3},[%4];"
        : "=r"(r[0]), "=r"(r[1]), "=r"(r[2]), "=r"(r[3]) : "r"(addr));
}
__device__ __forceinline__ void mma_bf16(float* c, const uint32_t* a, const uint32_t* b) {
    asm volatile("mma.sync.aligned.m16n8k16.row.col.f32.bf16.bf16.f32 "
        "{%0,%1,%2,%3},{%4,%5,%6,%7},{%8,%9},{%0,%1,%2,%3};"
        : "+f"(c[0]), "+f"(c[1]), "+f"(c[2]), "+f"(c[3])
        : "r"(a[0]), "r"(a[1]), "r"(a[2]), "r"(a[3]), "r"(b[0]), "r"(b[1]));
}
__device__ __forceinline__ void split2(float x0, float x1, uint32_t& hi, uint32_t& lo) {
    __nv_bfloat162 h = __floats2bfloat162_rn(x0, x1);
    hi = *(uint32_t*)&h;
    __nv_bfloat162 l = __floats2bfloat162_rn(x0 - __bfloat162float(h.x),
                                             x1 - __bfloat162float(h.y));
    lo = *(uint32_t*)&l;
}
__device__ __forceinline__ void split8(const float* o, uint4& h4, uint4& l4) {
    split2(o[0], o[1], h4.x, l4.x);
    split2(o[2], o[3], h4.y, l4.y);
    split2(o[4], o[5], h4.z, l4.z);
    split2(o[6], o[7], h4.w, l4.w);
}

// GEMM core: acc(16x64 per warp) = Ahi*Bhi + Alo*Bhi + Ahi*Blo
__device__ __forceinline__ void gemm_frags(
    float acc[8][4], const uint32_t Ah[4][4], const uint32_t Al[4][4],
    uint32_t wbaseH, uint32_t wbaseL, int lid)
{
    #pragma unroll
    for (int nt = 0; nt < 8; nt++)
        #pragma unroll
        for (int i = 0; i < 4; i++) acc[nt][i] = 0.f;
    const uint32_t colb = (uint32_t)(lid & 15) * RSTB + (uint32_t)(lid >> 4) * 16;
    #pragma unroll
    for (int p = 0; p < 4; p++) {
        const uint32_t cofs = colb + (uint32_t)(p * 32);
        uint32_t bh[4][4], bl[4][4];
        #pragma unroll
        for (int k = 0; k < 4; k++) ldsm4t(bh[k], wbaseH + (uint32_t)(k * 16) * RSTB + cofs);
        #pragma unroll
        for (int k = 0; k < 4; k++) { mma_bf16(acc[2*p], Ah[k], &bh[k][0]); mma_bf16(acc[2*p+1], Ah[k], &bh[k][2]); }
        #pragma unroll
        for (int k = 0; k < 4; k++) ldsm4t(bl[k], wbaseL + (uint32_t)(k * 16) * RSTB + cofs);
        #pragma unroll
        for (int k = 0; k < 4; k++) { mma_bf16(acc[2*p], Al[k], &bh[k][0]); mma_bf16(acc[2*p+1], Al[k], &bh[k][2]); }
        #pragma unroll
        for (int k = 0; k < 4; k++) { mma_bf16(acc[2*p], Ah[k], &bl[k][0]); mma_bf16(acc[2*p+1], Ah[k], &bl[k][2]); }
    }
}

// ======================= kernel 1: q/k/v projections (HMMA) =================
#define QOFF_W    0              // 3 x (hi 9216 + lo 9216) = 55296
#define QOFF_AH   55296
#define QOFF_AL   73728
#define QOFF_BIAS 92160          // 192 floats
#define QSMEM_BYTES 92928

__global__ __launch_bounds__(256, 2) void qkv_kernel(
    const float* __restrict__ feat,
    const float* __restrict__ wq, const float* __restrict__ bq,
    const float* __restrict__ wk, const float* __restrict__ bk,
    const float* __restrict__ wv, const float* __restrict__ bv,
    int n)
{
    extern __shared__ char qsm[];
    float* qbias = (float*)(qsm + QOFF_BIAS);
    const int t   = threadIdx.x;
    const int wid = t >> 5;
    const int lid = t & 31;
    const int row0 = blockIdx.x * 128;
    const uint32_t sbase = smem_u32(qsm);

    const float* Wm[3] = { wq, wk, wv };
    const float* Bm[3] = { bq, bk, bv };

    for (int idx = t; idx < 384; idx += 256) {
        const int m  = idx / 128;
        const int rw = (idx & 127) >> 1;
        const int hf = (idx & 1) * 32;
        const float* w = Wm[m];
        char* dH = qsm + QOFF_W + m * 18432 + rw * RSTB;
        char* dL = dH + 9216;
        #pragma unroll
        for (int c8 = 0; c8 < 32; c8 += 8) {
            int c = hf + c8;
            float o[8];
            float4 f0 = __ldg((const float4*)&w[rw * 64 + c]);
            float4 f1 = __ldg((const float4*)&w[rw * 64 + c + 4]);
            o[0]=f0.x; o[1]=f0.y; o[2]=f0.z; o[3]=f0.w;
            o[4]=f1.x; o[5]=f1.y; o[6]=f1.z; o[7]=f1.w;
            uint4 h4, l4;
            split8(o, h4, l4);
            *(uint4*)(dH + c * 2) = h4;
            *(uint4*)(dL + c * 2) = l4;
        }
    }
    if (t < 192) qbias[t] = __ldg(&Bm[t >> 6][t & 63]);

    {
        const int r  = t >> 1;
        const int hf = (t & 1) * 32;
        const int gr = row0 + r;
        char* pH = qsm + QOFF_AH + r * RSTB;
        char* pL = qsm + QOFF_AL + r * RSTB;
        #pragma unroll
        for (int c8 = 0; c8 < 32; c8 += 8) {
            int c = hf + c8;
            float o[8] = {0,0,0,0,0,0,0,0};
            if (gr < n) {
                float4 f0 = __ldg((const float4*)&feat[gr * 64 + c]);
                float4 f1 = __ldg((const float4*)&feat[gr * 64 + c + 4]);
                o[0]=f0.x; o[1]=f0.y; o[2]=f0.z; o[3]=f0.w;
                o[4]=f1.x; o[5]=f1.y; o[6]=f1.z; o[7]=f1.w;
            }
            uint4 h4, l4;
            split8(o, h4, l4);
            *(uint4*)(pH + c * 2) = h4;
            *(uint4*)(pL + c * 2) = l4;
        }
    }
    __syncthreads();

    const int q  = lid >> 3;
    const int rl = lid & 7;
    uint32_t aoff[4];
    #pragma unroll
    for (int k = 0; k < 4; k++)
        aoff[k] = (uint32_t)(wid * 16 + rl + (q & 1) * 8) * RSTB
                + (uint32_t)(k * 32) + (uint32_t)((q >> 1) * 16);
    uint32_t Ah[4][4], Al[4][4];
    #pragma unroll
    for (int k = 0; k < 4; k++) {
        ldsm4(Ah[k], sbase + QOFF_AH + aoff[k]);
        ldsm4(Al[k], sbase + QOFF_AL + aoff[k]);
    }

    const int dr = lid >> 2;
    const int dc = (lid & 3) * 2;
    float* Om[3] = { g_q, g_k, g_v };
    float acc[8][4];

    #pragma unroll
    for (int m = 0; m < 3; m++) {
        gemm_frags(acc, Ah, Al, sbase + QOFF_W + m * 18432,
                   sbase + QOFF_W + m * 18432 + 9216, lid);
        const int grA = row0 + wid * 16 + dr;
        const int grB = grA + 8;
        #pragma unroll
        for (int nt = 0; nt < 8; nt++) {
            int c = nt * 8 + dc;
            float b0 = qbias[m * 64 + c], b1 = qbias[m * 64 + c + 1];
            if (grA < n) *(float2*)&Om[m][grA * 64 + c] = make_float2(acc[nt][0] + b0, acc[nt][1] + b1);
            if (grB < n) *(float2*)&Om[m][grB * 64 + c] = make_float2(acc[nt][2] + b0, acc[nt][3] + b1);
        }
    }
}

// ======================= kernel 2: bf16 HMMA fused kernel (256 thr) =========
// Zero block barriers in main loop. Phase A is LINE-OPTIMAL: lane = 4 channels,
// 2 full gathered rows per LDG instruction (each 128B line touched once).
#define OFF_W1H  0
#define OFF_W1L  9216
#define OFF_W2H  18432
#define OFF_W2L  27648
#define OFF_AH   36864         // A tile hi; per-warp logits rows 0-7 overlay
#define OFF_AL   55296         // A tile lo; per-warp logits rows 8-15 overlay
#define OFF_STAT 73728         // rx,ry,rz,mu,rs (5*512B) + nb (512B)
#define OFF_SV   76800         // 768 floats
#define OFF_WO   79872         // wo staged fp32: 16384 bytes
#define OFF_SOF  96256         // s_o fp32: 8 warps x 4 sub-batches x 64 = 8192B
#define SMEM_BYTES 104448

__global__ __launch_bounds__(256, 2) void fused_kernel(
    const float* __restrict__ points,
    const float* __restrict__ feat,
    const int*   __restrict__ nbr,
    const float* __restrict__ wp,  const float* __restrict__ bp,
    const float* __restrict__ gp,  const float* __restrict__ betap,
    const float* __restrict__ wg1, const float* __restrict__ bg1,
    const float* __restrict__ gg,  const float* __restrict__ betag,
    const float* __restrict__ wg2, const float* __restrict__ bg2,
    const float* __restrict__ wo,  const float* __restrict__ bo,
    float* __restrict__ outp, int n)
{
    extern __shared__ char smb[];
    float* s_rx = (float*)(smb + OFF_STAT);
    float* s_ry = s_rx + 128;
    float* s_rz = s_ry + 128;
    float* s_mu = s_rz + 128;
    float* s_rs = s_mu + 128;
    int*   s_nb = (int*)(s_rs + 128);
    float* sv   = (float*)(smb + OFF_SV);
    float* wos  = (float*)(smb + OFF_WO);
    float* s_of = (float*)(smb + OFF_SOF);
    // sv: [0]=bg1 [64]=gg [128]=betag [192]=bg2 [256]=bp [320]=gp [384]=betap
    //     [448]=bo [512..704)=wp rows

    const int t   = threadIdx.x;
    const int wid = t >> 5;
    const int lid = t & 31;
    const uint32_t sbase = smem_u32(smb);

    if (t < 64) {
        sv[t]       = bg1[t];   sv[64 + t]  = gg[t];      sv[128 + t] = betag[t];
        sv[192 + t] = bg2[t];   sv[256 + t] = bp[t];      sv[320 + t] = gp[t];
        sv[384 + t] = betap[t]; sv[448 + t] = bo[t];
        sv[512 + t] = wp[t];    sv[576 + t] = wp[64 + t]; sv[640 + t] = wp[128 + t];
    }
    for (int i = t; i < 1024; i += 256)
        ((float4*)wos)[i] = __ldg(&((const float4*)wo)[i]);

    // ---- stage weights: bf16 hi/lo split, row-major [k][n], stride RSTB ----
    {
        const int rw  = t & 63;
        const int sel = t >> 6;
        const int m   = sel >> 1;
        const int hf  = (sel & 1) * 32;
        const float* w = m ? wg2 : wg1;
        char* dH = smb + (m ? OFF_W2H : OFF_W1H) + rw * RSTB;
        char* dL = smb + (m ? OFF_W2L : OFF_W1L) + rw * RSTB;
        #pragma unroll
        for (int c8 = 0; c8 < 32; c8 += 8) {
            int c = hf + c8;
            float o[8];
            float4 f0 = __ldg((const float4*)&w[rw * 64 + c]);
            float4 f1 = __ldg((const float4*)&w[rw * 64 + c + 4]);
            o[0]=f0.x; o[1]=f0.y; o[2]=f0.z; o[3]=f0.w;
            o[4]=f1.x; o[5]=f1.y; o[6]=f1.z; o[7]=f1.w;
            uint4 h4, l4;
            split8(o, h4, l4);
            *(uint4*)(dH + c * 2) = h4;
            *(uint4*)(dL + c * 2) = l4;
        }
    }
    __syncthreads();   // weights/sv/wos ready; ONLY block barrier in kernel

    // fragment geometry: warp wid owns rows [wid*16, wid*16+16) = ONE point
    const int q  = lid >> 3;
    const int rl = lid & 7;
    uint32_t aoff[4];
    #pragma unroll
    for (int k = 0; k < 4; k++)
        aoff[k] = (uint32_t)(wid * 16 + rl + (q & 1) * 8) * RSTB
                + (uint32_t)(k * 32) + (uint32_t)((q >> 1) * 16);
    const int dr  = lid >> 2;
    const int dc  = (lid & 3) * 2;
    const int rtl = (lid >> 3) & 3;
    const int cg  = lid & 7;
    const int c0  = cg * 8;
    const int hq  = lid & 15;     // channel quarter (4 ch)
    const int hh  = lid >> 4;     // row parity within phase-A iteration

    float acc[8][4];

    // per-warp neighbor prefetch: lanes 0..15 hold rows 0..15 of this point
    int nb_pref = 0;
    {
        int np0  = blockIdx.x * PPB + wid;
        int npc0 = (np0 < n) ? np0 : 0;
        if (lid < 16) nb_pref = __ldg(&nbr[npc0 * 16 + lid]);
    }

    for (int b = 0; b < 4; b++) {
        const int pbase = blockIdx.x * PPB + b * 8;
        const int pt  = pbase + wid;
        const int ptc = (pt < n) ? pt : 0;

        // ---------------- phase A (line-optimal): 8 iters x 2 rows ----------
        {
            int nbL = nb_pref;
            if (b < 3) {
                int np1  = pbase + 8 + wid;
                int npc1 = (np1 < n) ? np1 : 0;
                if (lid < 16) nb_pref = __ldg(&nbr[npc1 * 16 + lid]);
            }
            float bx = __ldg(&points[ptc * 3 + 0]);
            float by = __ldg(&points[ptc * 3 + 1]);
            float bz = __ldg(&points[ptc * 3 + 2]);
            float rxL = 0.f, ryL = 0.f, rzL = 0.f;
            if (lid < 16) {
                rxL = __ldg(&points[nbL * 3 + 0]) - bx;
                ryL = __ldg(&points[nbL * 3 + 1]) - by;
                rzL = __ldg(&points[nbL * 3 + 2]) - bz;
                int grow = wid * 16 + lid;
                s_rx[grow] = rxL; s_ry[grow] = ryL; s_rz[grow] = rzL;
                s_nb[grow] = nbL;
            }
            float4 q4 = *(const float4*)&g_q[(size_t)ptc * 64 + hq * 4];
            float wx[4], wy[4], wz[4], bp4[4], gp4[4], bt4[4];
            #pragma unroll
            for (int u = 0; u < 4; u++) {
                int c = hq * 4 + u;
                wx[u]  = sv[512 + c]; wy[u]  = sv[576 + c]; wz[u] = sv[640 + c];
                bp4[u] = sv[256 + c]; gp4[u] = sv[320 + c]; bt4[u] = sv[384 + c];
            }
            #pragma unroll
            for (int i = 0; i < 8; i++) {
                const int row = i * 2 + hh;   // local row 0..15
                int   nb_ = __shfl_sync(0xffffffffu, nbL, row);
                float rx  = __shfl_sync(0xffffffffu, rxL, row);
                float ry  = __shfl_sync(0xffffffffu, ryL, row);
                float rz  = __shfl_sync(0xffffffffu, rzL, row);
                float4 gk4 = *(const float4*)&g_k[(size_t)nb_ * 64 + hq * 4];
                float pre[4];
                float s1 = 0.f, s2 = 0.f;
                #pragma unroll
                for (int u = 0; u < 4; u++) {
                    pre[u] = fmaf(rx, wx[u], fmaf(ry, wy[u], fmaf(rz, wz[u], bp4[u])));
                    s1 += pre[u];
                    s2 = fmaf(pre[u], pre[u], s2);
                }
                #pragma unroll
                for (int mk = 1; mk < 16; mk <<= 1) {
                    s1 += __shfl_xor_sync(0xffffffffu, s1, mk);
                    s2 += __shfl_xor_sync(0xffffffffu, s2, mk);
                }
                float mu = s1 * 0.015625f;
                float rs = rsqrtf(s2 * 0.015625f - mu * mu + EPS);
                const int grow = wid * 16 + row;
                if (hq == 0) { s_mu[grow] = mu; s_rs[grow] = rs; }
                float o[4];
                #pragma unroll
                for (int u = 0; u < 4; u++) {
                    float p = fmaxf(fmaf((pre[u] - mu) * rs, gp4[u], bt4[u]), 0.f);
                    o[u] = (&q4.x)[u] - (&gk4.x)[u] + p;
                }
                uint32_t h0, l0, h1, l1;
                split2(o[0], o[1], h0, l0);
                split2(o[2], o[3], h1, l1);
                char* pH = smb + OFF_AH + grow * RSTB + hq * 8;
                char* pL = smb + OFF_AL + grow * RSTB + hq * 8;
                *(uint2*)pH = make_uint2(h0, h1);
                *(uint2*)pL = make_uint2(l0, l1);
            }
        }
        __syncwarp();

        // ---------------- GEMM1 (A-frags from own rows) ---------------------
        uint32_t Ah[4][4], Al[4][4];
        #pragma unroll
        for (int k = 0; k < 4; k++) {
            ldsm4(Ah[k], sbase + OFF_AH + aoff[k]);
            ldsm4(Al[k], sbase + OFF_AL + aoff[k]);
        }
        gemm_frags(acc, Ah, Al, sbase + OFF_W1H, sbase + OFF_W1L, lid);

        // ---------------- bias + in-fragment LN + relu -> A2 fragments ------
        uint32_t A2h[4][4], A2l[4][4];
        {
            float va[16], vb[16];
            float s1a = 0.f, s2a = 0.f, s1b = 0.f, s2b = 0.f;
            #pragma unroll
            for (int nt = 0; nt < 8; nt++) {
                int c = nt * 8 + dc;
                float x0 = acc[nt][0] + sv[c];
                float x1 = acc[nt][1] + sv[c + 1];
                float y0 = acc[nt][2] + sv[c];
                float y1 = acc[nt][3] + sv[c + 1];
                va[nt * 2] = x0; va[nt * 2 + 1] = x1;
                vb[nt * 2] = y0; vb[nt * 2 + 1] = y1;
                s1a += x0 + x1; s2a += fmaf(x0, x0, x1 * x1);
                s1b += y0 + y1; s2b += fmaf(y0, y0, y1 * y1);
            }
            #pragma unroll
            for (int mk = 1; mk < 4; mk <<= 1) {
                s1a += __shfl_xor_sync(0xffffffffu, s1a, mk);
                s2a += __shfl_xor_sync(0xffffffffu, s2a, mk);
                s1b += __shfl_xor_sync(0xffffffffu, s1b, mk);
                s2b += __shfl_xor_sync(0xffffffffu, s2b, mk);
            }
            float mua = s1a * 0.015625f;
            float rsa = rsqrtf(s2a * 0.015625f - mua * mua + EPS);
            float mub = s1b * 0.015625f;
            float rsb = rsqrtf(s2b * 0.015625f - mub * mub + EPS);
            #pragma unroll
            for (int nt = 0; nt < 8; nt++) {
                int c = nt * 8 + dc;
                float g0 = sv[64 + c], g1 = sv[64 + c + 1];
                float e0 = sv[128 + c], e1 = sv[128 + c + 1];
                float h0 = fmaxf(fmaf((va[nt*2]   - mua) * rsa, g0, e0), 0.f);
                float h1 = fmaxf(fmaf((va[nt*2+1] - mua) * rsa, g1, e1), 0.f);
                float h2 = fmaxf(fmaf((vb[nt*2]   - mub) * rsb, g0, e0), 0.f);
                float h3 = fmaxf(fmaf((vb[nt*2+1] - mub) * rsb, g1, e1), 0.f);
                int kt = nt >> 1, hhh = (nt & 1) * 2;
                split2(h0, h1, A2h[kt][hhh],     A2l[kt][hhh]);
                split2(h2, h3, A2h[kt][hhh + 1], A2l[kt][hhh + 1]);
            }
        }

        // ---------------- GEMM2 from register A-fragments -------------------
        gemm_frags(acc, A2h, A2l, sbase + OFF_W2H, sbase + OFF_W2L, lid);

        // ---------------- logits (+bg2) -> own per-warp chunks --------------
        {
            float* wrA = (float*)(smb + OFF_AH + wid * LCHB + dr * LRST);
            float* wrB = (float*)(smb + OFF_AL + wid * LCHB + dr * LRST);
            #pragma unroll
            for (int nt = 0; nt < 8; nt++) {
                int c = nt * 8 + dc;
                *(float2*)&wrA[c] = make_float2(acc[nt][0] + sv[192 + c], acc[nt][1] + sv[192 + c + 1]);
                *(float2*)&wrB[c] = make_float2(acc[nt][2] + sv[192 + c], acc[nt][3] + sv[192 + c + 1]);
            }
        }
        __syncwarp();

        // -------- softmax over neighbors + weighted sum (warp = point) ------
        {
            float lw[4][8];
            float4 gva[4], gvb[4];
            int rws[4];
            #pragma unroll
            for (int ii = 0; ii < 4; ii++) {
                int local = ii * 4 + rtl;
                int row = wid * 16 + local;
                rws[ii] = row;
                const float* wr = (const float*)(smb + (local < 8 ? OFF_AH : OFF_AL)
                                                 + wid * LCHB + (local & 7) * LRST);
                #pragma unroll
                for (int u = 0; u < 4; u++) {
                    float2 l2 = *(const float2*)&wr[c0 + 2 * u];
                    lw[ii][2 * u] = l2.x; lw[ii][2 * u + 1] = l2.y;
                }
                int nb2 = s_nb[row];
                gva[ii] = *(const float4*)&g_v[(size_t)nb2 * 64 + c0];
                gvb[ii] = *(const float4*)&g_v[(size_t)nb2 * 64 + c0 + 4];
            }
            float mx[8], se[8], wa[8], so[8];
            #pragma unroll
            for (int j = 0; j < 8; j++) {
                float m_ = fmaxf(fmaxf(lw[0][j], lw[1][j]), fmaxf(lw[2][j], lw[3][j]));
                m_ = fmaxf(m_, __shfl_xor_sync(0xffffffffu, m_, 8));
                m_ = fmaxf(m_, __shfl_xor_sync(0xffffffffu, m_, 16));
                mx[j] = m_; se[j] = 0.f; wa[j] = 0.f;
            }
            #pragma unroll
            for (int ii = 0; ii < 4; ii++) {
                int row = rws[ii];
                float rx = s_rx[row], ry = s_ry[row], rz = s_rz[row];
                float mu = s_mu[row], rs = s_rs[row];
                #pragma unroll
                for (int j = 0; j < 8; j++) {
                    int c = c0 + j;
                    float pre = fmaf(rx, sv[512 + c], fmaf(ry, sv[576 + c], fmaf(rz, sv[640 + c], sv[256 + c])));
                    float p = fmaxf(fmaf((pre - mu) * rs, sv[320 + c], sv[384 + c]), 0.f);
                    float gvv = (j < 4) ? (&gva[ii].x)[j] : (&gvb[ii].x)[j - 4];
                    float e = __expf(lw[ii][j] - mx[j]);
                    se[j] += e;
                    wa[j] = fmaf(e, gvv + p, wa[j]);
                }
            }
            #pragma unroll
            for (int j = 0; j < 8; j++) {
                se[j] += __shfl_xor_sync(0xffffffffu, se[j], 8);
                se[j] += __shfl_xor_sync(0xffffffffu, se[j], 16);
                wa[j] += __shfl_xor_sync(0xffffffffu, wa[j], 8);
                wa[j] += __shfl_xor_sync(0xffffffffu, wa[j], 16);
                so[j] = wa[j] / se[j];
            }
            // lanes rtl==0 (lid 0..7) cover all 64 channels: spill fp32 s_o row
            if (rtl == 0) {
                float* dst = &s_of[wid * 256 + b * 64 + c0];
                *(float4*)dst       = make_float4(so[0], so[1], so[2], so[3]);
                *(float4*)(dst + 4) = make_float4(so[4], so[5], so[6], so[7]);
            }
        }
        // no block barrier between sub-batches (all state warp-private)
    }

    // ---------------- deferred per-warp epilogue: 4 points, wo read ONCE ----
    __syncwarp();
    {
        const int pbase0 = blockIdx.x * PPB + wid;  // points pbase0 + 8*p
        float a0[4], a1[4];
        #pragma unroll
        for (int p = 0; p < 4; p++) {
            a0[p] = sv[448 + lid];
            a1[p] = sv[448 + lid + 32];
        }
        const float* sw = &s_of[wid * 256];
        #pragma unroll 4
        for (int k4 = 0; k4 < 64; k4 += 4) {
            float4 s4[4];
            #pragma unroll
            for (int p = 0; p < 4; p++) s4[p] = *(const float4*)&sw[p * 64 + k4];
            #pragma unroll
            for (int ku = 0; ku < 4; ku++) {
                int k = k4 + ku;
                float w0 = wos[k * 64 + lid];
                float w1 = wos[k * 64 + lid + 32];
                #pragma unroll
                for (int p = 0; p < 4; p++) {
                    float s_ = (&s4[p].x)[ku];
                    a0[p] = fmaf(s_, w0, a0[p]);
                    a1[p] = fmaf(s_, w1, a1[p]);
                }
            }
        }
        #pragma unroll
        for (int p = 0; p < 4; p++) {
            int pt = pbase0 + p * 8;
            if (pt < n) {
                outp[pt * 64 + lid]      = a0[p] + __ldg(&feat[pt * 64 + lid]);
                outp[pt * 64 + lid + 32] = a1[p] + __ldg(&feat[pt * 64 + lid + 32]);
            }
        }
    }
}

// ======================= launch =============================================
extern "C" void kernel_launch(void* const* d_in, const int* in_sizes, int n_in,
                              void* d_out, int out_size)
{
    const float* points = (const float*)d_in[0];
    const float* feat   = (const float*)d_in[1];
    const int*   nbr    = (const int*)  d_in[2];
    const float* wq = (const float*)d_in[3];
    const float* bq = (const float*)d_in[4];
    const float* wk = (const float*)d_in[5];
    const float* bk = (const float*)d_in[6];
    const float* wv = (const float*)d_in[7];
    const float* bv = (const float*)d_in[8];
    const float* wp = (const float*)d_in[9];
    const float* bp = (const float*)d_in[10];
    const float* gp = (const float*)d_in[11];
    const float* betap = (const float*)d_in[12];
    const float* wg1 = (const float*)d_in[13];
    const float* bg1 = (const float*)d_in[14];
    const float* gg  = (const float*)d_in[15];
    const float* betag = (const float*)d_in[16];
    const float* wg2 = (const float*)d_in[17];
    const float* bg2 = (const float*)d_in[18];
    const float* wo  = (const float*)d_in[19];
    const float* bo  = (const float*)d_in[20];
    float* outp = (float*)d_out;

    int n = in_sizes[1] / 64;
    if (n > NMAX) n = NMAX;

    cudaFuncSetAttribute(qkv_kernel, cudaFuncAttributeMaxDynamicSharedMemorySize, QSMEM_BYTES);
    qkv_kernel<<<(n + 127) / 128, 256, QSMEM_BYTES>>>(feat, wq, bq, wk, bk, wv, bv, n);

    cudaFuncSetAttribute(fused_kernel, cudaFuncAttributeMaxDynamicSharedMemorySize, SMEM_BYTES);
    fused_kernel<<<(n + PPB - 1) / PPB, 256, SMEM_BYTES>>>(
        points, feat, nbr,
        wp, bp, gp, betap,
        wg1, bg1, gg, betag,
        wg2, bg2, wo, bo,
        outp, n);
}